// round 11
// baseline (speedup 1.0000x reference)
#include <cuda_runtime.h>
#include <math.h>

#define HIDDEN 150
#define EMBED 300
#define OUTC 5
#define DEPTH 13
#define NN 8191          // 2^13 - 1
#define LL 4096          // leaves
#define LEAF_START 4095  // 2^12 - 1
#define BK 20            // 300 = 15 * 20
#define NPAD_L 480       // padded leaf columns (>= 160*3)
#define NPAD_U 800       // padded inner columns (>= 160*5)

// ---------------- device scratch (no allocs allowed) ----------------
__device__ float g_H[NN * HIDDEN];
__device__ float g_C[NN * HIDDEN];
// transposed, gate-interleaved, column-PADDED weights: WT[k][n], n = j*GATES + gate
__device__ float g_WLt[EMBED * NPAD_L];
__device__ float g_WUt[EMBED * NPAD_U];
// row-major copy for warp_level tail
__device__ float g_WUi[750 * EMBED];
__device__ float g_bLi[480];
__device__ float g_bUi[800];

__device__ __forceinline__ float sigmoidf(float x) {
    return 1.0f / (1.0f + expf(-x));
}

// ---------------- weight stacking ----------------
__global__ void prep_kernel(
    const float* __restrict__ Wi, const float* __restrict__ bi,
    const float* __restrict__ Wo, const float* __restrict__ bo,
    const float* __restrict__ Wu, const float* __restrict__ bu,
    const float* __restrict__ U0i, const float* __restrict__ U1i, const float* __restrict__ bbi,
    const float* __restrict__ U00f, const float* __restrict__ U01f,
    const float* __restrict__ U10f, const float* __restrict__ U11f, const float* __restrict__ bbf,
    const float* __restrict__ U0o, const float* __restrict__ U1o, const float* __restrict__ bbo,
    const float* __restrict__ U0u, const float* __restrict__ U1u, const float* __restrict__ bbu)
{
    int t = blockIdx.x * blockDim.x + threadIdx.x;
    int stride = gridDim.x * blockDim.x;

    for (int idx = t; idx < EMBED * NPAD_L; idx += stride) {
        int k = idx / NPAD_L, n = idx % NPAD_L;
        float v = 0.0f;
        if (n < 450) {
            int j = n / 3, g = n % 3;
            const float* W = (g == 0) ? Wi : (g == 1) ? Wo : Wu;
            v = W[j * EMBED + k];
        }
        g_WLt[idx] = v;
    }
    for (int idx = t; idx < EMBED * NPAD_U; idx += stride) {
        int k = idx / NPAD_U, n = idx % NPAD_U;
        float v = 0.0f;
        if (n < 750) {
            int j = n / 5, g = n % 5;
            const float* U0; const float* U1;
            switch (g) {
                case 0:  U0 = U0i;  U1 = U1i;  break;
                case 1:  U0 = U00f; U1 = U01f; break;
                case 2:  U0 = U10f; U1 = U11f; break;
                case 3:  U0 = U0o;  U1 = U1o;  break;
                default: U0 = U0u;  U1 = U1u;  break;
            }
            v = (k < HIDDEN) ? U0[j * HIDDEN + k] : U1[j * HIDDEN + (k - HIDDEN)];
            g_WUi[n * EMBED + k] = v;
        }
        g_WUt[idx] = v;
    }
    if (t < 480) {
        float v = 0.0f;
        if (t < 450) {
            int j = t / 3, g = t % 3;
            v = (g == 0) ? bi[j] : (g == 1) ? bo[j] : bu[j];
        }
        g_bLi[t] = v;
    }
    if (t < 800) {
        float v = 0.0f;
        if (t < 750) {
            int j = t / 5, g = t % 5;
            v = (g == 0) ? bbi[j] : (g <= 2) ? bbf[j] : (g == 3) ? bbo[j] : bbu[j];
        }
        g_bUi[t] = v;
    }
}

// ---------------- fused tiled GEMM + activation (double-buffered, no div/mod in loop) --------
// thread tile: ROWS rows x 1 j x GATES gates. Requires M % BM == 0.
template<int GATES, int MODE, int BM, int BJ, int ROWS>
__global__ __launch_bounds__((BM / ROWS) * BJ)
void fused_level(int s, int M,
                 const float* __restrict__ emb,
                 const int* __restrict__ words)
{
    constexpr int THREADS = (BM / ROWS) * BJ;
    constexpr int WCOLS = BJ * GATES;
    constexpr int NTOTP = (MODE == 0) ? NPAD_L : NPAD_U;
    constexpr int AELEMS = BM * BK;
    constexpr int WELEMS = WCOLS * BK;
    constexpr int LA = (AELEMS + THREADS - 1) / THREADS;
    constexpr int LW = (WELEMS + THREADS - 1) / THREADS;
    static_assert(LA * THREADS < 2 * AELEMS, "A wrap-around requires <2x overshoot");
    static_assert(LW * THREADS < 2 * WELEMS, "W wrap-around requires <2x overshoot");
    constexpr int NT = EMBED / BK;     // 15 k-tiles

    __shared__ float As[2][BK][BM];
    __shared__ float Ws[2][BK][WCOLS];
    __shared__ int   rowOff[BM];

    const float* __restrict__ WT    = (MODE == 0) ? g_WLt : g_WUt;
    const float* __restrict__ Abase = (MODE == 0) ? emb : (g_H + (2 * s + 1) * HIDDEN);
    const float* __restrict__ bias  = (MODE == 0) ? g_bLi : g_bUi;

    int bm = blockIdx.x * BM;
    int j0 = blockIdx.y * BJ;
    int n0 = j0 * GATES;
    int tid = threadIdx.x;
    int tx = tid % BJ, ty = tid / BJ;

    for (int e = tid; e < BM; e += THREADS) {
        int m = bm + e;
        rowOff[e] = (MODE == 0) ? words[LEAF_START + m] * EMBED : m * EMBED;
    }
    __syncthreads();

    // ---- precomputed index tables (all div/mod done once) ----
    int aGOff[LA], aSOff[LA];
    #pragma unroll
    for (int l = 0; l < LA; l++) {
        int e = tid + l * THREADS;
        if (e >= AELEMS) e -= AELEMS;
        int ml = e / BK, kk = e % BK;
        aGOff[l] = rowOff[ml] + kk;      // + k0 per tile
        aSOff[l] = kk * BM + ml;
    }
    int wGOff[LW], wSOff[LW];
    #pragma unroll
    for (int l = 0; l < LW; l++) {
        int e = tid + l * THREADS;
        if (e >= WELEMS) e -= WELEMS;
        int kk = e / WCOLS, nl = e % WCOLS;
        wGOff[l] = kk * NTOTP + n0 + nl; // + k0*NTOTP per tile
        wSOff[l] = kk * WCOLS + nl;
    }

    float* AsF = &As[0][0][0];
    float* WsF = &Ws[0][0][0];
    constexpr int ABUF = BK * BM;
    constexpr int WBUF = BK * WCOLS;

    float ra[LA], rw[LW];
    auto fetch = [&](int k0) {
        #pragma unroll
        for (int l = 0; l < LA; l++) ra[l] = Abase[aGOff[l] + k0];
        int wk = k0 * NTOTP;
        #pragma unroll
        for (int l = 0; l < LW; l++) rw[l] = WT[wGOff[l] + wk];
    };
    auto stage = [&](int boff_a, int boff_w) {
        #pragma unroll
        for (int l = 0; l < LA; l++) AsF[boff_a + aSOff[l]] = ra[l];
        #pragma unroll
        for (int l = 0; l < LW; l++) WsF[boff_w + wSOff[l]] = rw[l];
    };

    float acc[ROWS][GATES];
    #pragma unroll
    for (int i = 0; i < ROWS; i++)
        #pragma unroll
        for (int g = 0; g < GATES; g++)
            acc[i][g] = 0.0f;

    fetch(0);
    stage(0, 0);
    __syncthreads();

    #pragma unroll 1
    for (int t = 0; t < NT; t++) {
        int b = t & 1;
        if (t + 1 < NT) fetch((t + 1) * BK);

        const float* Ab = AsF + b * ABUF;
        const float* Wb = WsF + b * WBUF;
        #pragma unroll
        for (int kk = 0; kk < BK; kk++) {
            float a[ROWS], w[GATES];
            if (ROWS == 8) {
                float4 av0 = *reinterpret_cast<const float4*>(Ab + kk * BM + ty * 8);
                float4 av1 = *reinterpret_cast<const float4*>(Ab + kk * BM + ty * 8 + 4);
                a[0] = av0.x; a[1] = av0.y; a[2] = av0.z; a[3] = av0.w;
                a[4] = av1.x; a[5] = av1.y; a[6] = av1.z; a[7] = av1.w;
            } else if (ROWS == 4) {
                float4 av = *reinterpret_cast<const float4*>(Ab + kk * BM + ty * 4);
                a[0] = av.x; a[1] = av.y; a[2] = av.z; a[3] = av.w;
            } else if (ROWS == 2) {
                float2 av = *reinterpret_cast<const float2*>(Ab + kk * BM + ty * 2);
                a[0] = av.x; a[1] = av.y;
            } else {
                #pragma unroll
                for (int i = 0; i < ROWS; i++) a[i] = Ab[kk * BM + ty * ROWS + i];
            }
            #pragma unroll
            for (int g = 0; g < GATES; g++) w[g] = Wb[kk * WCOLS + tx * GATES + g];
            #pragma unroll
            for (int i = 0; i < ROWS; i++)
                #pragma unroll
                for (int g = 0; g < GATES; g++)
                    acc[i][g] += a[i] * w[g];
        }
        if (t + 1 < NT) stage((b ^ 1) * ABUF, (b ^ 1) * WBUF);
        __syncthreads();
    }

    int j = j0 + tx;
    if (j >= HIDDEN) return;
    int nb = j * GATES;
    #pragma unroll
    for (int i = 0; i < ROWS; i++) {
        int m = bm + ty * ROWS + i;
        if (MODE == 0) {
            float ig = sigmoidf(acc[i][0] + bias[nb + 0]);
            float og = sigmoidf(acc[i][1] + bias[nb + 1]);
            float uv = tanhf   (acc[i][2] + bias[nb + 2]);
            float c = ig * uv;
            float h = og * tanhf(c);
            int node = LEAF_START + m;
            g_H[node * HIDDEN + j] = h;
            g_C[node * HIDDEN + j] = c;
        } else {
            float ig = sigmoidf(acc[i][0] + bias[nb + 0]);
            float fl = sigmoidf(acc[i][1] + bias[nb + 1]);
            float fr = sigmoidf(acc[i][2] + bias[nb + 2]);
            float og = sigmoidf(acc[i][3] + bias[nb + 3]);
            float uv = tanhf   (acc[i][4] + bias[nb + 4]);
            int node = s + m;
            float lc = g_C[(2 * node + 1) * HIDDEN + j];
            float rc = g_C[(2 * node + 2) * HIDDEN + j];
            float c = ig * uv + fl * lc + fr * rc;
            float h = og * tanhf(c);
            g_H[node * HIDDEN + j] = h;
            g_C[node * HIDDEN + j] = c;
        }
    }
}

// ---------------- warp-per-(node, j) kernel for tiny levels ----------------
__global__ void warp_level(int s, int M)
{
    int wid  = (blockIdx.x * blockDim.x + threadIdx.x) >> 5;
    int lane = threadIdx.x & 31;
    int m = wid / HIDDEN;
    int j = wid % HIDDEN;
    if (m >= M) return;

    const float* __restrict__ A  = g_H + (2 * s + 1 + 2 * m) * HIDDEN;  // 300 contiguous
    const float* __restrict__ Wr = g_WUi + (j * 5) * EMBED;

    float a0 = 0.f, a1 = 0.f, a2 = 0.f, a3 = 0.f, a4 = 0.f;
    #pragma unroll
    for (int kb = 0; kb < EMBED; kb += 32) {
        int k = kb + lane;
        float a = A[k];
        a0 += a * Wr[k];
        a1 += a * Wr[EMBED + k];
        a2 += a * Wr[2 * EMBED + k];
        a3 += a * Wr[3 * EMBED + k];
        a4 += a * Wr[4 * EMBED + k];
    }
    #pragma unroll
    for (int d = 16; d > 0; d >>= 1) {
        a0 += __shfl_xor_sync(0xffffffff, a0, d);
        a1 += __shfl_xor_sync(0xffffffff, a1, d);
        a2 += __shfl_xor_sync(0xffffffff, a2, d);
        a3 += __shfl_xor_sync(0xffffffff, a3, d);
        a4 += __shfl_xor_sync(0xffffffff, a4, d);
    }
    if (lane == 0) {
        int nb = j * 5;
        float ig = sigmoidf(a0 + g_bUi[nb + 0]);
        float fl = sigmoidf(a1 + g_bUi[nb + 1]);
        float fr = sigmoidf(a2 + g_bUi[nb + 2]);
        float og = sigmoidf(a3 + g_bUi[nb + 3]);
        float uv = tanhf   (a4 + g_bUi[nb + 4]);
        int node = s + m;
        float lc = g_C[(2 * node + 1) * HIDDEN + j];
        float rc = g_C[(2 * node + 2) * HIDDEN + j];
        float c = ig * uv + fl * lc + fr * rc;
        float h = og * tanhf(c);
        g_H[node * HIDDEN + j] = h;
        g_C[node * HIDDEN + j] = c;
    }
}

// ---------------- loss ----------------
__global__ void zero_out(float* out)
{
    if (threadIdx.x == 0 && blockIdx.x == 0) out[0] = 0.0f;
}

__global__ void loss_kernel(const float* __restrict__ Why,
                            const float* __restrict__ by,
                            const int*   __restrict__ scores,
                            float* __restrict__ out)
{
    int gw   = (blockIdx.x * blockDim.x + threadIdx.x) >> 5;
    int lane = threadIdx.x & 31;
    if (gw >= NN) return;

    const float* h = g_H + gw * HIDDEN;
    float logits[OUTC];
    #pragma unroll
    for (int o = 0; o < OUTC; o++) {
        float sacc = 0.0f;
        for (int k = lane; k < HIDDEN; k += 32)
            sacc += Why[o * HIDDEN + k] * h[k];
        #pragma unroll
        for (int d = 16; d > 0; d >>= 1)
            sacc += __shfl_xor_sync(0xffffffff, sacc, d);
        logits[o] = sacc + by[o];
    }
    if (lane == 0) {
        float mx = logits[0];
        #pragma unroll
        for (int o = 1; o < OUTC; o++) mx = fmaxf(mx, logits[o]);
        float se = 0.0f;
        #pragma unroll
        for (int o = 0; o < OUTC; o++) se += expf(logits[o] - mx);
        float lse = mx + logf(se);
        int sc = scores[gw];
        atomicAdd(out, lse - logits[sc]);
    }
}

// ---------------- launch ----------------
extern "C" void kernel_launch(void* const* d_in, const int* in_sizes, int n_in,
                              void* d_out, int out_size)
{
    const float* Wi   = (const float*)d_in[0];
    const float* bi   = (const float*)d_in[1];
    const float* Wo   = (const float*)d_in[2];
    const float* bo   = (const float*)d_in[3];
    const float* Wu   = (const float*)d_in[4];
    const float* bu   = (const float*)d_in[5];
    const float* U0i  = (const float*)d_in[6];
    const float* U1i  = (const float*)d_in[7];
    const float* bbi  = (const float*)d_in[8];
    const float* U00f = (const float*)d_in[9];
    const float* U01f = (const float*)d_in[10];
    const float* U10f = (const float*)d_in[11];
    const float* U11f = (const float*)d_in[12];
    const float* bbf  = (const float*)d_in[13];
    const float* U0o  = (const float*)d_in[14];
    const float* U1o  = (const float*)d_in[15];
    const float* bbo  = (const float*)d_in[16];
    const float* U0u  = (const float*)d_in[17];
    const float* U1u  = (const float*)d_in[18];
    const float* bbu  = (const float*)d_in[19];
    const float* Why  = (const float*)d_in[20];
    const float* by   = (const float*)d_in[21];
    const float* emb  = (const float*)d_in[22];
    const int*   scores = (const int*)d_in[23];
    const int*   words  = (const int*)d_in[24];

    float* out = (float*)d_out;

    zero_out<<<1, 32>>>(out);
    prep_kernel<<<240, 256>>>(Wi, bi, Wo, bo, Wu, bu,
                              U0i, U1i, bbi,
                              U00f, U01f, U10f, U11f, bbf,
                              U0o, U1o, bbo,
                              U0u, U1u, bbu);

    // leaf: M=4096, GATES=3 — BM=64, BJ=16, ROWS=8 (128 thr), grid (64,10)=640
    {
        dim3 grid(LL / 64, (HIDDEN + 15) / 16);
        fused_level<3, 0, 64, 16, 8><<<grid, 128>>>(0, LL, emb, words);
    }

    // d=11,10: BM=64, BJ=16, ROWS=8 (128 thr) — grids 320 / 160
    for (int d = 11; d >= 10; d--) {
        int s = (1 << d) - 1, M = 1 << d;
        dim3 grid(M / 64, (HIDDEN + 15) / 16);
        fused_level<5, 1, 64, 16, 8><<<grid, 128>>>(s, M, nullptr, nullptr);
    }

    // d=9,8: BM=32, BJ=16, ROWS=4 (128 thr) — grids 160 / 80
    for (int d = 9; d >= 8; d--) {
        int s = (1 << d) - 1, M = 1 << d;
        dim3 grid(M / 32, (HIDDEN + 15) / 16);
        fused_level<5, 1, 32, 16, 4><<<grid, 128>>>(s, M, nullptr, nullptr);
    }

    // d=7,6: BM=16, BJ=16, ROWS=2 (128 thr) — grids 80 / 40
    for (int d = 7; d >= 6; d--) {
        int s = (1 << d) - 1, M = 1 << d;
        dim3 grid(M / 16, (HIDDEN + 15) / 16);
        fused_level<5, 1, 16, 16, 2><<<grid, 128>>>(s, M, nullptr, nullptr);
    }

    // d=5..0: warp per (node, j)
    for (int d = 5; d >= 0; d--) {
        int s = (1 << d) - 1, M = 1 << d;
        int warps = M * HIDDEN;
        int blocks = (warps + 7) / 8;
        warp_level<<<blocks, 256>>>(s, M);
    }

    // final loss over all 8191 nodes
    {
        int blocks = (NN + 7) / 8;
        loss_kernel<<<blocks, 256>>>(Why, by, scores, out);
    }
    (void)in_sizes; (void)n_in; (void)out_size;
}

// round 12
// speedup vs baseline: 1.0581x; 1.0581x over previous
#include <cuda_runtime.h>
#include <math.h>
#include <stdint.h>

#define HIDDEN 150
#define EMBED 300
#define OUTC 5
#define DEPTH 13
#define NN 8191          // 2^13 - 1
#define LL 4096          // leaves
#define LEAF_START 4095  // 2^12 - 1
#define BK 20            // 300 = 15 * 20
#define NPAD_L 480       // padded leaf columns (>= 160*3)
#define NPAD_U 800       // padded inner columns (>= 160*5)

// ---------------- device scratch (no allocs allowed) ----------------
__device__ float g_H[NN * HIDDEN];
__device__ float g_C[NN * HIDDEN];
// transposed, gate-interleaved, column-PADDED weights: WT[k][n], n = j*GATES + gate
__device__ float g_WLt[EMBED * NPAD_L];
__device__ float g_WUt[EMBED * NPAD_U];
// row-major copy for warp_level tail
__device__ float g_WUi[750 * EMBED];
__device__ float g_bLi[480];
__device__ float g_bUi[800];

__device__ __forceinline__ float sigmoidf(float x) {
    return 1.0f / (1.0f + expf(-x));
}

__device__ __forceinline__ unsigned smem_u32(const void* p) {
    return (unsigned)__cvta_generic_to_shared(p);
}
__device__ __forceinline__ void cp_async16(unsigned dst, const void* src) {
    asm volatile("cp.async.ca.shared.global [%0], [%1], 16;" :: "r"(dst), "l"(src));
}
__device__ __forceinline__ void cp_async_commit() {
    asm volatile("cp.async.commit_group;" ::: "memory");
}
__device__ __forceinline__ void cp_async_wait0() {
    asm volatile("cp.async.wait_group 0;" ::: "memory");
}

// ---------------- weight stacking ----------------
__global__ void prep_kernel(
    const float* __restrict__ Wi, const float* __restrict__ bi,
    const float* __restrict__ Wo, const float* __restrict__ bo,
    const float* __restrict__ Wu, const float* __restrict__ bu,
    const float* __restrict__ U0i, const float* __restrict__ U1i, const float* __restrict__ bbi,
    const float* __restrict__ U00f, const float* __restrict__ U01f,
    const float* __restrict__ U10f, const float* __restrict__ U11f, const float* __restrict__ bbf,
    const float* __restrict__ U0o, const float* __restrict__ U1o, const float* __restrict__ bbo,
    const float* __restrict__ U0u, const float* __restrict__ U1u, const float* __restrict__ bbu)
{
    int t = blockIdx.x * blockDim.x + threadIdx.x;
    int stride = gridDim.x * blockDim.x;

    for (int idx = t; idx < EMBED * NPAD_L; idx += stride) {
        int k = idx / NPAD_L, n = idx % NPAD_L;
        float v = 0.0f;
        if (n < 450) {
            int j = n / 3, g = n % 3;
            const float* W = (g == 0) ? Wi : (g == 1) ? Wo : Wu;
            v = W[j * EMBED + k];
        }
        g_WLt[idx] = v;
    }
    for (int idx = t; idx < EMBED * NPAD_U; idx += stride) {
        int k = idx / NPAD_U, n = idx % NPAD_U;
        float v = 0.0f;
        if (n < 750) {
            int j = n / 5, g = n % 5;
            const float* U0; const float* U1;
            switch (g) {
                case 0:  U0 = U0i;  U1 = U1i;  break;
                case 1:  U0 = U00f; U1 = U01f; break;
                case 2:  U0 = U10f; U1 = U11f; break;
                case 3:  U0 = U0o;  U1 = U1o;  break;
                default: U0 = U0u;  U1 = U1u;  break;
            }
            v = (k < HIDDEN) ? U0[j * HIDDEN + k] : U1[j * HIDDEN + (k - HIDDEN)];
            g_WUi[n * EMBED + k] = v;
        }
        g_WUt[idx] = v;
    }
    if (t < 480) {
        float v = 0.0f;
        if (t < 450) {
            int j = t / 3, g = t % 3;
            v = (g == 0) ? bi[j] : (g == 1) ? bo[j] : bu[j];
        }
        g_bLi[t] = v;
    }
    if (t < 800) {
        float v = 0.0f;
        if (t < 750) {
            int j = t / 5, g = t % 5;
            v = (g == 0) ? bbi[j] : (g <= 2) ? bbf[j] : (g == 3) ? bbo[j] : bbu[j];
        }
        g_bUi[t] = v;
    }
}

// ---------------- fused tiled GEMM + activation --------------------------------
// double-buffered; A via LDG+STS (transposed), W via cp.async (contiguous rows).
// thread tile: ROWS rows x 1 j x GATES gates. Requires M % BM == 0.
template<int GATES, int MODE, int BM, int BJ, int ROWS>
__global__ __launch_bounds__((BM / ROWS) * BJ)
void fused_level(int s, int M,
                 const float* __restrict__ emb,
                 const int* __restrict__ words)
{
    constexpr int THREADS = (BM / ROWS) * BJ;
    constexpr int WCOLS = BJ * GATES;
    static_assert(WCOLS % 4 == 0, "W row must be float4-divisible");
    constexpr int NTOTP = (MODE == 0) ? NPAD_L : NPAD_U;
    constexpr int AELEMS = BM * BK;
    constexpr int LA = (AELEMS + THREADS - 1) / THREADS;
    static_assert(LA * THREADS < 2 * AELEMS, "A wrap-around requires <2x overshoot");
    constexpr int WC4 = WCOLS / 4;             // float4 per kk row
    constexpr int WELEMS4 = BK * WC4;
    constexpr int LW4 = (WELEMS4 + THREADS - 1) / THREADS;
    static_assert(LW4 * THREADS < 2 * WELEMS4, "W wrap-around requires <2x overshoot");
    constexpr int NT = EMBED / BK;             // 15 k-tiles

    __shared__ __align__(16) float As[2][BK][BM];
    __shared__ __align__(16) float Ws[2][BK][WCOLS];
    __shared__ int rowOff[BM];

    const float* __restrict__ WT    = (MODE == 0) ? g_WLt : g_WUt;
    const float* __restrict__ Abase = (MODE == 0) ? emb : (g_H + (2 * s + 1) * HIDDEN);
    const float* __restrict__ bias  = (MODE == 0) ? g_bLi : g_bUi;

    int bm = blockIdx.x * BM;
    int j0 = blockIdx.y * BJ;
    int n0 = j0 * GATES;
    int tid = threadIdx.x;
    int tx = tid % BJ, ty = tid / BJ;

    for (int e = tid; e < BM; e += THREADS) {
        int m = bm + e;
        rowOff[e] = (MODE == 0) ? words[LEAF_START + m] * EMBED : m * EMBED;
    }
    __syncthreads();

    // ---- precomputed index tables (all div/mod done once) ----
    int aGOff[LA], aSOff[LA];
    #pragma unroll
    for (int l = 0; l < LA; l++) {
        int e = tid + l * THREADS;
        if (e >= AELEMS) e -= AELEMS;
        int ml = e / BK, kk = e % BK;
        aGOff[l] = rowOff[ml] + kk;      // + k0 per tile
        aSOff[l] = kk * BM + ml;
    }
    int wG4[LW4];                        // float offsets into WT (+ k0*NTOTP per tile)
    unsigned wS4[LW4];                   // byte offsets within one Ws buffer
    #pragma unroll
    for (int l = 0; l < LW4; l++) {
        int e4 = tid + l * THREADS;
        if (e4 >= WELEMS4) e4 -= WELEMS4;
        int kk = e4 / WC4, nl4 = e4 % WC4;
        wG4[l] = kk * NTOTP + n0 + nl4 * 4;
        wS4[l] = (unsigned)((kk * WCOLS + nl4 * 4) * 4);
    }

    float* AsF = &As[0][0][0];
    const unsigned wsBase = smem_u32(&Ws[0][0][0]);
    constexpr int ABUF = BK * BM;
    constexpr unsigned WBUF_BYTES = (unsigned)(BK * WCOLS * 4);

    float ra[LA];
    auto fetchA = [&](int k0) {
        #pragma unroll
        for (int l = 0; l < LA; l++) ra[l] = Abase[aGOff[l] + k0];
    };
    auto stageA = [&](int boff_a) {
        #pragma unroll
        for (int l = 0; l < LA; l++) AsF[boff_a + aSOff[l]] = ra[l];
    };
    auto fetchW = [&](int k0, int b) {
        int wk = k0 * NTOTP;
        unsigned base = wsBase + (unsigned)b * WBUF_BYTES;
        #pragma unroll
        for (int l = 0; l < LW4; l++)
            cp_async16(base + wS4[l], WT + wG4[l] + wk);
        cp_async_commit();
    };

    float acc[ROWS][GATES];
    #pragma unroll
    for (int i = 0; i < ROWS; i++)
        #pragma unroll
        for (int g = 0; g < GATES; g++)
            acc[i][g] = 0.0f;

    fetchA(0);
    fetchW(0, 0);
    stageA(0);
    cp_async_wait0();
    __syncthreads();

    #pragma unroll 1
    for (int t = 0; t < NT; t++) {
        int b = t & 1;
        if (t + 1 < NT) {
            fetchA((t + 1) * BK);
            fetchW((t + 1) * BK, b ^ 1);
        }

        const float* Ab = AsF + b * ABUF;
        const float* Wb = &Ws[0][0][0] + b * (BK * WCOLS);
        #pragma unroll
        for (int kk = 0; kk < BK; kk++) {
            float a[ROWS], w[GATES];
            if (ROWS == 4) {
                float4 av = *reinterpret_cast<const float4*>(Ab + kk * BM + ty * 4);
                a[0] = av.x; a[1] = av.y; a[2] = av.z; a[3] = av.w;
            } else if (ROWS == 2) {
                float2 av = *reinterpret_cast<const float2*>(Ab + kk * BM + ty * 2);
                a[0] = av.x; a[1] = av.y;
            } else {
                #pragma unroll
                for (int i = 0; i < ROWS; i++) a[i] = Ab[kk * BM + ty * ROWS + i];
            }
            #pragma unroll
            for (int g = 0; g < GATES; g++) w[g] = Wb[kk * WCOLS + tx * GATES + g];
            #pragma unroll
            for (int i = 0; i < ROWS; i++)
                #pragma unroll
                for (int g = 0; g < GATES; g++)
                    acc[i][g] += a[i] * w[g];
        }
        if (t + 1 < NT) {
            stageA((b ^ 1) * ABUF);
            cp_async_wait0();
        }
        __syncthreads();
    }

    int j = j0 + tx;
    if (j >= HIDDEN) return;
    int nb = j * GATES;
    #pragma unroll
    for (int i = 0; i < ROWS; i++) {
        int m = bm + ty * ROWS + i;
        if (MODE == 0) {
            float ig = sigmoidf(acc[i][0] + bias[nb + 0]);
            float og = sigmoidf(acc[i][1] + bias[nb + 1]);
            float uv = tanhf   (acc[i][2] + bias[nb + 2]);
            float c = ig * uv;
            float h = og * tanhf(c);
            int node = LEAF_START + m;
            g_H[node * HIDDEN + j] = h;
            g_C[node * HIDDEN + j] = c;
        } else {
            float ig = sigmoidf(acc[i][0] + bias[nb + 0]);
            float fl = sigmoidf(acc[i][1] + bias[nb + 1]);
            float fr = sigmoidf(acc[i][2] + bias[nb + 2]);
            float og = sigmoidf(acc[i][3] + bias[nb + 3]);
            float uv = tanhf   (acc[i][4] + bias[nb + 4]);
            int node = s + m;
            float lc = g_C[(2 * node + 1) * HIDDEN + j];
            float rc = g_C[(2 * node + 2) * HIDDEN + j];
            float c = ig * uv + fl * lc + fr * rc;
            float h = og * tanhf(c);
            g_H[node * HIDDEN + j] = h;
            g_C[node * HIDDEN + j] = c;
        }
    }
}

// ---------------- warp-per-(node, j) kernel for tiny levels ----------------
__global__ void warp_level(int s, int M)
{
    int wid  = (blockIdx.x * blockDim.x + threadIdx.x) >> 5;
    int lane = threadIdx.x & 31;
    int m = wid / HIDDEN;
    int j = wid % HIDDEN;
    if (m >= M) return;

    const float* __restrict__ A  = g_H + (2 * s + 1 + 2 * m) * HIDDEN;  // 300 contiguous
    const float* __restrict__ Wr = g_WUi + (j * 5) * EMBED;

    float a0 = 0.f, a1 = 0.f, a2 = 0.f, a3 = 0.f, a4 = 0.f;
    #pragma unroll
    for (int kb = 0; kb < EMBED; kb += 32) {
        int k = kb + lane;
        float a = A[k];
        a0 += a * Wr[k];
        a1 += a * Wr[EMBED + k];
        a2 += a * Wr[2 * EMBED + k];
        a3 += a * Wr[3 * EMBED + k];
        a4 += a * Wr[4 * EMBED + k];
    }
    #pragma unroll
    for (int d = 16; d > 0; d >>= 1) {
        a0 += __shfl_xor_sync(0xffffffff, a0, d);
        a1 += __shfl_xor_sync(0xffffffff, a1, d);
        a2 += __shfl_xor_sync(0xffffffff, a2, d);
        a3 += __shfl_xor_sync(0xffffffff, a3, d);
        a4 += __shfl_xor_sync(0xffffffff, a4, d);
    }
    if (lane == 0) {
        int nb = j * 5;
        float ig = sigmoidf(a0 + g_bUi[nb + 0]);
        float fl = sigmoidf(a1 + g_bUi[nb + 1]);
        float fr = sigmoidf(a2 + g_bUi[nb + 2]);
        float og = sigmoidf(a3 + g_bUi[nb + 3]);
        float uv = tanhf   (a4 + g_bUi[nb + 4]);
        int node = s + m;
        float lc = g_C[(2 * node + 1) * HIDDEN + j];
        float rc = g_C[(2 * node + 2) * HIDDEN + j];
        float c = ig * uv + fl * lc + fr * rc;
        float h = og * tanhf(c);
        g_H[node * HIDDEN + j] = h;
        g_C[node * HIDDEN + j] = c;
    }
}

// ---------------- loss ----------------
__global__ void zero_out(float* out)
{
    if (threadIdx.x == 0 && blockIdx.x == 0) out[0] = 0.0f;
}

__global__ void loss_kernel(const float* __restrict__ Why,
                            const float* __restrict__ by,
                            const int*   __restrict__ scores,
                            float* __restrict__ out)
{
    int gw   = (blockIdx.x * blockDim.x + threadIdx.x) >> 5;
    int lane = threadIdx.x & 31;
    if (gw >= NN) return;

    const float* h = g_H + gw * HIDDEN;
    float logits[OUTC];
    #pragma unroll
    for (int o = 0; o < OUTC; o++) {
        float sacc = 0.0f;
        for (int k = lane; k < HIDDEN; k += 32)
            sacc += Why[o * HIDDEN + k] * h[k];
        #pragma unroll
        for (int d = 16; d > 0; d >>= 1)
            sacc += __shfl_xor_sync(0xffffffff, sacc, d);
        logits[o] = sacc + by[o];
    }
    if (lane == 0) {
        float mx = logits[0];
        #pragma unroll
        for (int o = 1; o < OUTC; o++) mx = fmaxf(mx, logits[o]);
        float se = 0.0f;
        #pragma unroll
        for (int o = 0; o < OUTC; o++) se += expf(logits[o] - mx);
        float lse = mx + logf(se);
        int sc = scores[gw];
        atomicAdd(out, lse - logits[sc]);
    }
}

// ---------------- launch ----------------
extern "C" void kernel_launch(void* const* d_in, const int* in_sizes, int n_in,
                              void* d_out, int out_size)
{
    const float* Wi   = (const float*)d_in[0];
    const float* bi   = (const float*)d_in[1];
    const float* Wo   = (const float*)d_in[2];
    const float* bo   = (const float*)d_in[3];
    const float* Wu   = (const float*)d_in[4];
    const float* bu   = (const float*)d_in[5];
    const float* U0i  = (const float*)d_in[6];
    const float* U1i  = (const float*)d_in[7];
    const float* bbi  = (const float*)d_in[8];
    const float* U00f = (const float*)d_in[9];
    const float* U01f = (const float*)d_in[10];
    const float* U10f = (const float*)d_in[11];
    const float* U11f = (const float*)d_in[12];
    const float* bbf  = (const float*)d_in[13];
    const float* U0o  = (const float*)d_in[14];
    const float* U1o  = (const float*)d_in[15];
    const float* bbo  = (const float*)d_in[16];
    const float* U0u  = (const float*)d_in[17];
    const float* U1u  = (const float*)d_in[18];
    const float* bbu  = (const float*)d_in[19];
    const float* Why  = (const float*)d_in[20];
    const float* by   = (const float*)d_in[21];
    const float* emb  = (const float*)d_in[22];
    const int*   scores = (const int*)d_in[23];
    const int*   words  = (const int*)d_in[24];

    float* out = (float*)d_out;

    zero_out<<<1, 32>>>(out);
    prep_kernel<<<240, 256>>>(Wi, bi, Wo, bo, Wu, bu,
                              U0i, U1i, bbi,
                              U00f, U01f, U10f, U11f, bbf,
                              U0o, U1o, bbo,
                              U0u, U1u, bbu);

    // leaf: M=4096, GATES=3 — BM=32, BJ=16, ROWS=4 (128 thr), grid (128,10)=1280
    {
        dim3 grid(LL / 32, (HIDDEN + 15) / 16);
        fused_level<3, 0, 32, 16, 4><<<grid, 128>>>(0, LL, emb, words);
    }

    // d=11..8: BM=32, BJ=16, ROWS=4 (128 thr) — grids 640, 320, 160, 80
    for (int d = 11; d >= 8; d--) {
        int s = (1 << d) - 1, M = 1 << d;
        dim3 grid(M / 32, (HIDDEN + 15) / 16);
        fused_level<5, 1, 32, 16, 4><<<grid, 128>>>(s, M, nullptr, nullptr);
    }

    // d=7,6: BM=16, BJ=16, ROWS=2 (128 thr) — grids 80 / 40
    for (int d = 7; d >= 6; d--) {
        int s = (1 << d) - 1, M = 1 << d;
        dim3 grid(M / 16, (HIDDEN + 15) / 16);
        fused_level<5, 1, 16, 16, 2><<<grid, 128>>>(s, M, nullptr, nullptr);
    }

    // d=5..0: warp per (node, j)
    for (int d = 5; d >= 0; d--) {
        int s = (1 << d) - 1, M = 1 << d;
        int warps = M * HIDDEN;
        int blocks = (warps + 7) / 8;
        warp_level<<<blocks, 256>>>(s, M);
    }

    // final loss over all 8191 nodes
    {
        int blocks = (NN + 7) / 8;
        loss_kernel<<<blocks, 256>>>(Why, by, scores, out);
    }
    (void)in_sizes; (void)n_in; (void)out_size;
}

// round 13
// speedup vs baseline: 1.6101x; 1.5217x over previous
#include <cuda_runtime.h>
#include <math.h>
#include <stdint.h>

#define HIDDEN 150
#define EMBED 300
#define OUTC 5
#define DEPTH 13
#define NN 8191          // 2^13 - 1
#define LL 4096          // leaves
#define LEAF_START 4095  // 2^12 - 1
#define KPAD 312         // K padded to 13 * 24
#define NPAD_L 480       // padded leaf columns (>= 160*3)
#define NPAD_U 800       // padded inner columns (>= 160*5)

// ---------------- device scratch (no allocs allowed) ----------------
__device__ float g_H[NN * HIDDEN + 64];   // small pad for safety
__device__ float g_C[NN * HIDDEN];
// transposed, gate-interleaved, K- and N-padded TF32 weights: WT[k][n], n = j*GATES + g
__device__ float g_WLt[KPAD * NPAD_L];
__device__ float g_WUt[KPAD * NPAD_U];
// row-major fp32 copy for warp_level tail
__device__ float g_WUi[750 * EMBED];
__device__ float g_bLi[480];
__device__ float g_bUi[800];

__device__ __forceinline__ float sigmoidf(float x) {
    return 1.0f / (1.0f + expf(-x));
}
__device__ __forceinline__ float to_tf32(float v) {
    float r;
    asm("cvt.rna.tf32.f32 %0, %1;" : "=f"(r) : "f"(v));
    return r;
}
__device__ __forceinline__ unsigned smem_u32(const void* p) {
    return (unsigned)__cvta_generic_to_shared(p);
}
__device__ __forceinline__ void cp_async16(unsigned dst, const void* src) {
    asm volatile("cp.async.ca.shared.global [%0], [%1], 16;" :: "r"(dst), "l"(src));
}
__device__ __forceinline__ void cp_async8(unsigned dst, const void* src) {
    asm volatile("cp.async.ca.shared.global [%0], [%1], 8;" :: "r"(dst), "l"(src));
}
__device__ __forceinline__ void cp_async8_sz(unsigned dst, const void* src, int sz) {
    asm volatile("cp.async.ca.shared.global [%0], [%1], 8, %2;" :: "r"(dst), "l"(src), "r"(sz));
}
__device__ __forceinline__ void cp_async_commit() {
    asm volatile("cp.async.commit_group;" ::: "memory");
}
__device__ __forceinline__ void cp_async_wait0() {
    asm volatile("cp.async.wait_group 0;" ::: "memory");
}
__device__ __forceinline__ void mma_tf32(float& c0, float& c1, float& c2, float& c3,
                                         unsigned a0, unsigned a1, unsigned a2, unsigned a3,
                                         unsigned b0, unsigned b1) {
    asm volatile(
        "mma.sync.aligned.m16n8k8.row.col.f32.tf32.tf32.f32 "
        "{%0,%1,%2,%3}, {%4,%5,%6,%7}, {%8,%9}, {%0,%1,%2,%3};"
        : "+f"(c0), "+f"(c1), "+f"(c2), "+f"(c3)
        : "r"(a0), "r"(a1), "r"(a2), "r"(a3), "r"(b0), "r"(b1));
}

// ---------------- weight stacking (tf32, K- and N-padded) ----------------
__global__ void prep_kernel(
    const float* __restrict__ Wi, const float* __restrict__ bi,
    const float* __restrict__ Wo, const float* __restrict__ bo,
    const float* __restrict__ Wu, const float* __restrict__ bu,
    const float* __restrict__ U0i, const float* __restrict__ U1i, const float* __restrict__ bbi,
    const float* __restrict__ U00f, const float* __restrict__ U01f,
    const float* __restrict__ U10f, const float* __restrict__ U11f, const float* __restrict__ bbf,
    const float* __restrict__ U0o, const float* __restrict__ U1o, const float* __restrict__ bbo,
    const float* __restrict__ U0u, const float* __restrict__ U1u, const float* __restrict__ bbu)
{
    int t = blockIdx.x * blockDim.x + threadIdx.x;
    int stride = gridDim.x * blockDim.x;

    for (int idx = t; idx < KPAD * NPAD_L; idx += stride) {
        int k = idx / NPAD_L, n = idx % NPAD_L;
        float v = 0.0f;
        if (n < 450 && k < EMBED) {
            int j = n / 3, g = n % 3;
            const float* W = (g == 0) ? Wi : (g == 1) ? Wo : Wu;
            v = to_tf32(W[j * EMBED + k]);
        }
        g_WLt[idx] = v;
    }
    for (int idx = t; idx < KPAD * NPAD_U; idx += stride) {
        int k = idx / NPAD_U, n = idx % NPAD_U;
        float v = 0.0f;
        if (n < 750 && k < EMBED) {
            int j = n / 5, g = n % 5;
            const float* U0; const float* U1;
            switch (g) {
                case 0:  U0 = U0i;  U1 = U1i;  break;
                case 1:  U0 = U00f; U1 = U01f; break;
                case 2:  U0 = U10f; U1 = U11f; break;
                case 3:  U0 = U0o;  U1 = U1o;  break;
                default: U0 = U0u;  U1 = U1u;  break;
            }
            float raw = (k < HIDDEN) ? U0[j * HIDDEN + k] : U1[j * HIDDEN + (k - HIDDEN)];
            g_WUi[n * EMBED + k] = raw;   // full-precision copy for warp_level
            v = to_tf32(raw);
        }
        g_WUt[idx] = v;
    }
    if (t < 480) {
        float v = 0.0f;
        if (t < 450) {
            int j = t / 3, g = t % 3;
            v = (g == 0) ? bi[j] : (g == 1) ? bo[j] : bu[j];
        }
        g_bLi[t] = v;
    }
    if (t < 800) {
        float v = 0.0f;
        if (t < 750) {
            int j = t / 5, g = t % 5;
            v = (g == 0) ? bbi[j] : (g <= 2) ? bbf[j] : (g == 3) ? bbo[j] : bbu[j];
        }
        g_bUi[t] = v;
    }
}

// ---------------- tensor-core fused level (tf32 mma.sync) ----------------
// Block: 128 threads = 4 warps, each warp owns a 16-row slice of BM=64.
// Tile: BM=64 x BN=(16 j's * GATES); K tiles of 24 (3 k8 steps), double-buffered.
template<int GATES, int MODE>
__global__ __launch_bounds__(128)
void mma_level(int s, int M,
               const float* __restrict__ emb,
               const int* __restrict__ words)
{
    constexpr int BM = 64, BJ = 16;
    constexpr int BN = BJ * GATES;          // 48 leaf / 80 inner
    constexpr int NT8 = BN / 8;             // 6 / 10
    constexpr int BK = 24;
    constexpr int NT = KPAD / BK;           // 13
    constexpr int AP = 28;                  // A smem row stride (16B aligned, conflict-free)
    constexpr int WP = (GATES == 5) ? 88 : 56;  // W smem row stride (16B aligned, conflict-free)
    constexpr int NPAD = (MODE == 0) ? NPAD_L : NPAD_U;

    constexpr int ACH = BM * (BK / 2);      // 8B chunks for A: 768
    constexpr int LAC = ACH / 128;          // 6
    constexpr int WCH = BK * (BN / 4);      // 16B chunks for W: 288 / 480
    constexpr int LWC = (WCH + 127) / 128;  // 3 / 4 (wrap)

    constexpr int ABUF = BM * AP;           // floats per A buffer
    constexpr int WBUF = BK * WP;
    constexpr int SMEMFL = 2 * ABUF + 2 * WBUF;

    __shared__ __align__(16) float SB[SMEMFL];
    __shared__ int rowOff[BM];

    float* AsF = SB;
    float* WsF = SB + 2 * ABUF;
    float* Cs  = SB;                        // overlay, used after the K loop

    const float* __restrict__ WT    = (MODE == 0) ? g_WLt : g_WUt;
    const float* __restrict__ Abase = (MODE == 0) ? emb : g_H;
    const float* __restrict__ bias  = (MODE == 0) ? g_bLi : g_bUi;

    int tid = threadIdx.x;
    int warp = tid >> 5, lane = tid & 31;
    int gid = lane >> 2, tig = lane & 3;
    int m0 = warp * 16;
    int bm = blockIdx.x * BM;
    int j0 = blockIdx.y * BJ;
    int n0 = j0 * GATES;

    for (int e = tid; e < BM; e += 128) {
        int m = bm + e;
        rowOff[e] = (MODE == 0) ? words[LEAF_START + m] * EMBED
                                : (2 * s + 1) * HIDDEN + m * EMBED;
    }
    __syncthreads();

    // ---- A chunk tables: 8B chunks, 12 per row ----
    int aSrc[LAC]; unsigned aDst[LAC]; int aLastB[LAC];
    #pragma unroll
    for (int l = 0; l < LAC; l++) {
        int idx = tid + l * 128;
        int m = idx / 12, c = idx % 12;
        aSrc[l] = rowOff[m] + 2 * c;
        aDst[l] = smem_u32(AsF) + (unsigned)((m * AP + 2 * c) * 4);
        int rem = (12 - 2 * c) * 4;        // valid bytes in last tile (k0=288, 12 valid floats)
        aLastB[l] = rem < 0 ? 0 : (rem > 8 ? 8 : rem);
    }
    // ---- W chunk tables: 16B chunks ----
    int wSrc[LWC]; unsigned wDst[LWC];
    #pragma unroll
    for (int l = 0; l < LWC; l++) {
        int idx = tid + l * 128;
        if (idx >= WCH) idx -= WCH;        // wrap: benign duplicate copy
        int kk = idx / (BN / 4), n4 = idx % (BN / 4);
        wSrc[l] = kk * NPAD + n0 + n4 * 4;
        wDst[l] = smem_u32(WsF) + (unsigned)((kk * WP + n4 * 4) * 4);
    }

    auto fetch = [&](int t, int b) {
        int k0 = t * BK;
        unsigned aoff = (unsigned)(b * ABUF * 4);
        if (t == NT - 1) {
            #pragma unroll
            for (int l = 0; l < LAC; l++) {
                const float* src = Abase + (aLastB[l] > 0 ? aSrc[l] + k0 : aSrc[l]);
                cp_async8_sz(aDst[l] + aoff, src, aLastB[l]);
            }
        } else {
            #pragma unroll
            for (int l = 0; l < LAC; l++)
                cp_async8(aDst[l] + aoff, Abase + aSrc[l] + k0);
        }
        unsigned woff = (unsigned)(b * WBUF * 4);
        int wk = k0 * NPAD;
        #pragma unroll
        for (int l = 0; l < LWC; l++)
            cp_async16(wDst[l] + woff, WT + wSrc[l] + wk);
        cp_async_commit();
    };

    float c[NT8][4];
    #pragma unroll
    for (int nt = 0; nt < NT8; nt++)
        #pragma unroll
        for (int q = 0; q < 4; q++)
            c[nt][q] = 0.0f;

    fetch(0, 0);
    cp_async_wait0();
    __syncthreads();

    #pragma unroll 1
    for (int t = 0; t < NT; t++) {
        int b = t & 1;
        if (t + 1 < NT) fetch(t + 1, b ^ 1);

        const float* Ab = AsF + b * ABUF;
        const float* Wb = WsF + b * WBUF;
        #pragma unroll
        for (int ks = 0; ks < 3; ks++) {
            int kb = ks * 8;
            unsigned a0 = __float_as_uint(to_tf32(Ab[(m0 + gid) * AP + kb + tig]));
            unsigned a1 = __float_as_uint(to_tf32(Ab[(m0 + gid + 8) * AP + kb + tig]));
            unsigned a2 = __float_as_uint(to_tf32(Ab[(m0 + gid) * AP + kb + tig + 4]));
            unsigned a3 = __float_as_uint(to_tf32(Ab[(m0 + gid + 8) * AP + kb + tig + 4]));
            #pragma unroll
            for (int nt = 0; nt < NT8; nt++) {
                unsigned b0 = __float_as_uint(Wb[(kb + tig) * WP + nt * 8 + gid]);
                unsigned b1 = __float_as_uint(Wb[(kb + tig + 4) * WP + nt * 8 + gid]);
                mma_tf32(c[nt][0], c[nt][1], c[nt][2], c[nt][3], a0, a1, a2, a3, b0, b1);
            }
        }
        if (t + 1 < NT) cp_async_wait0();
        __syncthreads();
    }

    // ---- C fragments -> smem (overlay) ----
    #pragma unroll
    for (int nt = 0; nt < NT8; nt++) {
        Cs[(m0 + gid) * WP + nt * 8 + tig * 2]         = c[nt][0];
        Cs[(m0 + gid) * WP + nt * 8 + tig * 2 + 1]     = c[nt][1];
        Cs[(m0 + gid + 8) * WP + nt * 8 + tig * 2]     = c[nt][2];
        Cs[(m0 + gid + 8) * WP + nt * 8 + tig * 2 + 1] = c[nt][3];
    }
    __syncthreads();

    // ---- fused activation epilogue ----
    #pragma unroll
    for (int it = 0; it < (BM * BJ) / 128; it++) {
        int idx = tid + it * 128;
        int jl = idx >> 6;          // 0..15
        int m = idx & 63;
        int j = j0 + jl;
        if (j >= HIDDEN) continue;
        int nb = j * GATES;
        const float* cv = Cs + m * WP + jl * GATES;
        if (MODE == 0) {
            float ig = sigmoidf(cv[0] + bias[nb + 0]);
            float og = sigmoidf(cv[1] + bias[nb + 1]);
            float uv = tanhf   (cv[2] + bias[nb + 2]);
            float cc = ig * uv;
            float h = og * tanhf(cc);
            int node = LEAF_START + bm + m;
            g_H[node * HIDDEN + j] = h;
            g_C[node * HIDDEN + j] = cc;
        } else {
            float ig = sigmoidf(cv[0] + bias[nb + 0]);
            float fl = sigmoidf(cv[1] + bias[nb + 1]);
            float fr = sigmoidf(cv[2] + bias[nb + 2]);
            float og = sigmoidf(cv[3] + bias[nb + 3]);
            float uv = tanhf   (cv[4] + bias[nb + 4]);
            int node = s + bm + m;
            float lc = g_C[(2 * node + 1) * HIDDEN + j];
            float rc = g_C[(2 * node + 2) * HIDDEN + j];
            float cc = ig * uv + fl * lc + fr * rc;
            float h = og * tanhf(cc);
            g_H[node * HIDDEN + j] = h;
            g_C[node * HIDDEN + j] = cc;
        }
    }
}

// ---------------- scalar fused level (for small levels d7,d6) ----------------
template<int GATES, int MODE, int BM, int BJ, int ROWS>
__global__ __launch_bounds__((BM / ROWS) * BJ)
void fused_level(int s, int M,
                 const float* __restrict__ emb,
                 const int* __restrict__ words)
{
    constexpr int THREADS = (BM / ROWS) * BJ;
    constexpr int WCOLS = BJ * GATES;
    constexpr int NTOTP = (MODE == 0) ? NPAD_L : NPAD_U;
    constexpr int BKS = 20;
    constexpr int AELEMS = BM * BKS;
    constexpr int WELEMS = WCOLS * BKS;
    constexpr int LA = (AELEMS + THREADS - 1) / THREADS;
    constexpr int LW = (WELEMS + THREADS - 1) / THREADS;
    constexpr int NTS = EMBED / BKS;   // 15

    __shared__ float As[2][BKS][BM];
    __shared__ float Ws[2][BKS][WCOLS];
    __shared__ int rowOff[BM];

    const float* __restrict__ WT    = (MODE == 0) ? g_WLt : g_WUt;
    const float* __restrict__ Abase = (MODE == 0) ? emb : (g_H + (2 * s + 1) * HIDDEN);
    const float* __restrict__ bias  = (MODE == 0) ? g_bLi : g_bUi;

    int bm = blockIdx.x * BM;
    int j0 = blockIdx.y * BJ;
    int n0 = j0 * GATES;
    int tid = threadIdx.x;
    int tx = tid % BJ, ty = tid / BJ;

    for (int e = tid; e < BM; e += THREADS) {
        int m = bm + e;
        rowOff[e] = (MODE == 0) ? words[LEAF_START + m] * EMBED : m * EMBED;
    }
    __syncthreads();

    int aGOff[LA], aSOff[LA];
    #pragma unroll
    for (int l = 0; l < LA; l++) {
        int e = tid + l * THREADS;
        if (e >= AELEMS) e -= AELEMS;
        int ml = e / BKS, kk = e % BKS;
        aGOff[l] = rowOff[ml] + kk;
        aSOff[l] = kk * BM + ml;
    }
    int wGOff[LW], wSOff[LW];
    #pragma unroll
    for (int l = 0; l < LW; l++) {
        int e = tid + l * THREADS;
        if (e >= WELEMS) e -= WELEMS;
        int kk = e / WCOLS, nl = e % WCOLS;
        wGOff[l] = kk * NTOTP + n0 + nl;
        wSOff[l] = kk * WCOLS + nl;
    }

    float* AsF = &As[0][0][0];
    float* WsF = &Ws[0][0][0];
    constexpr int ABUF = BKS * BM;
    constexpr int WBUF = BKS * WCOLS;

    float ra[LA], rw[LW];
    auto fetch = [&](int k0) {
        #pragma unroll
        for (int l = 0; l < LA; l++) ra[l] = Abase[aGOff[l] + k0];
        int wk = k0 * NTOTP;
        #pragma unroll
        for (int l = 0; l < LW; l++) rw[l] = WT[wGOff[l] + wk];
    };
    auto stage = [&](int boff_a, int boff_w) {
        #pragma unroll
        for (int l = 0; l < LA; l++) AsF[boff_a + aSOff[l]] = ra[l];
        #pragma unroll
        for (int l = 0; l < LW; l++) WsF[boff_w + wSOff[l]] = rw[l];
    };

    float acc[ROWS][GATES];
    #pragma unroll
    for (int i = 0; i < ROWS; i++)
        #pragma unroll
        for (int g = 0; g < GATES; g++)
            acc[i][g] = 0.0f;

    fetch(0);
    stage(0, 0);
    __syncthreads();

    #pragma unroll 1
    for (int t = 0; t < NTS; t++) {
        int b = t & 1;
        if (t + 1 < NTS) fetch((t + 1) * BKS);
        const float* Ab = AsF + b * ABUF;
        const float* Wb = WsF + b * WBUF;
        #pragma unroll
        for (int kk = 0; kk < BKS; kk++) {
            float a[ROWS], w[GATES];
            #pragma unroll
            for (int i = 0; i < ROWS; i++) a[i] = Ab[kk * BM + ty * ROWS + i];
            #pragma unroll
            for (int g = 0; g < GATES; g++) w[g] = Wb[kk * WCOLS + tx * GATES + g];
            #pragma unroll
            for (int i = 0; i < ROWS; i++)
                #pragma unroll
                for (int g = 0; g < GATES; g++)
                    acc[i][g] += a[i] * w[g];
        }
        if (t + 1 < NTS) stage((b ^ 1) * ABUF, (b ^ 1) * WBUF);
        __syncthreads();
    }

    int j = j0 + tx;
    if (j >= HIDDEN) return;
    int nb = j * GATES;
    #pragma unroll
    for (int i = 0; i < ROWS; i++) {
        int m = bm + ty * ROWS + i;
        float ig = sigmoidf(acc[i][0] + bias[nb + 0]);
        float fl = sigmoidf(acc[i][1] + bias[nb + 1]);
        float fr = sigmoidf(acc[i][2] + bias[nb + 2]);
        float og = sigmoidf(acc[i][3] + bias[nb + 3]);
        float uv = tanhf   (acc[i][4] + bias[nb + 4]);
        int node = s + m;
        float lc = g_C[(2 * node + 1) * HIDDEN + j];
        float rc = g_C[(2 * node + 2) * HIDDEN + j];
        float cc = ig * uv + fl * lc + fr * rc;
        float h = og * tanhf(cc);
        g_H[node * HIDDEN + j] = h;
        g_C[node * HIDDEN + j] = cc;
    }
}

// ---------------- warp-per-(node, j) kernel for tiny levels ----------------
__global__ void warp_level(int s, int M)
{
    int wid  = (blockIdx.x * blockDim.x + threadIdx.x) >> 5;
    int lane = threadIdx.x & 31;
    int m = wid / HIDDEN;
    int j = wid % HIDDEN;
    if (m >= M) return;

    const float* __restrict__ A  = g_H + (2 * s + 1 + 2 * m) * HIDDEN;
    const float* __restrict__ Wr = g_WUi + (j * 5) * EMBED;

    float a0 = 0.f, a1 = 0.f, a2 = 0.f, a3 = 0.f, a4 = 0.f;
    #pragma unroll
    for (int kb = 0; kb < EMBED; kb += 32) {
        int k = kb + lane;
        float a = A[k];
        a0 += a * Wr[k];
        a1 += a * Wr[EMBED + k];
        a2 += a * Wr[2 * EMBED + k];
        a3 += a * Wr[3 * EMBED + k];
        a4 += a * Wr[4 * EMBED + k];
    }
    #pragma unroll
    for (int d = 16; d > 0; d >>= 1) {
        a0 += __shfl_xor_sync(0xffffffff, a0, d);
        a1 += __shfl_xor_sync(0xffffffff, a1, d);
        a2 += __shfl_xor_sync(0xffffffff, a2, d);
        a3 += __shfl_xor_sync(0xffffffff, a3, d);
        a4 += __shfl_xor_sync(0xffffffff, a4, d);
    }
    if (lane == 0) {
        int nb = j * 5;
        float ig = sigmoidf(a0 + g_bUi[nb + 0]);
        float fl = sigmoidf(a1 + g_bUi[nb + 1]);
        float fr = sigmoidf(a2 + g_bUi[nb + 2]);
        float og = sigmoidf(a3 + g_bUi[nb + 3]);
        float uv = tanhf   (a4 + g_bUi[nb + 4]);
        int node = s + m;
        float lc = g_C[(2 * node + 1) * HIDDEN + j];
        float rc = g_C[(2 * node + 2) * HIDDEN + j];
        float c = ig * uv + fl * lc + fr * rc;
        float h = og * tanhf(c);
        g_H[node * HIDDEN + j] = h;
        g_C[node * HIDDEN + j] = c;
    }
}

// ---------------- loss ----------------
__global__ void zero_out(float* out)
{
    if (threadIdx.x == 0 && blockIdx.x == 0) out[0] = 0.0f;
}

__global__ void loss_kernel(const float* __restrict__ Why,
                            const float* __restrict__ by,
                            const int*   __restrict__ scores,
                            float* __restrict__ out)
{
    int gw   = (blockIdx.x * blockDim.x + threadIdx.x) >> 5;
    int lane = threadIdx.x & 31;
    if (gw >= NN) return;

    const float* h = g_H + gw * HIDDEN;
    float logits[OUTC];
    #pragma unroll
    for (int o = 0; o < OUTC; o++) {
        float sacc = 0.0f;
        for (int k = lane; k < HIDDEN; k += 32)
            sacc += Why[o * HIDDEN + k] * h[k];
        #pragma unroll
        for (int d = 16; d > 0; d >>= 1)
            sacc += __shfl_xor_sync(0xffffffff, sacc, d);
        logits[o] = sacc + by[o];
    }
    if (lane == 0) {
        float mx = logits[0];
        #pragma unroll
        for (int o = 1; o < OUTC; o++) mx = fmaxf(mx, logits[o]);
        float se = 0.0f;
        #pragma unroll
        for (int o = 0; o < OUTC; o++) se += expf(logits[o] - mx);
        float lse = mx + logf(se);
        int sc = scores[gw];
        atomicAdd(out, lse - logits[sc]);
    }
}

// ---------------- launch ----------------
extern "C" void kernel_launch(void* const* d_in, const int* in_sizes, int n_in,
                              void* d_out, int out_size)
{
    const float* Wi   = (const float*)d_in[0];
    const float* bi   = (const float*)d_in[1];
    const float* Wo   = (const float*)d_in[2];
    const float* bo   = (const float*)d_in[3];
    const float* Wu   = (const float*)d_in[4];
    const float* bu   = (const float*)d_in[5];
    const float* U0i  = (const float*)d_in[6];
    const float* U1i  = (const float*)d_in[7];
    const float* bbi  = (const float*)d_in[8];
    const float* U00f = (const float*)d_in[9];
    const float* U01f = (const float*)d_in[10];
    const float* U10f = (const float*)d_in[11];
    const float* U11f = (const float*)d_in[12];
    const float* bbf  = (const float*)d_in[13];
    const float* U0o  = (const float*)d_in[14];
    const float* U1o  = (const float*)d_in[15];
    const float* bbo  = (const float*)d_in[16];
    const float* U0u  = (const float*)d_in[17];
    const float* U1u  = (const float*)d_in[18];
    const float* bbu  = (const float*)d_in[19];
    const float* Why  = (const float*)d_in[20];
    const float* by   = (const float*)d_in[21];
    const float* emb  = (const float*)d_in[22];
    const int*   scores = (const int*)d_in[23];
    const int*   words  = (const int*)d_in[24];

    float* out = (float*)d_out;

    zero_out<<<1, 32>>>(out);
    prep_kernel<<<240, 256>>>(Wi, bi, Wo, bo, Wu, bu,
                              U0i, U1i, bbi,
                              U00f, U01f, U10f, U11f, bbf,
                              U0o, U1o, bbo,
                              U0u, U1u, bbu);

    // leaf: M=4096 — tensor cores, grid (64, 10)
    {
        dim3 grid(LL / 64, 10);
        mma_level<3, 0><<<grid, 128>>>(0, LL, emb, words);
    }

    // d=11..8: tensor cores — grids (32..4, 10)
    for (int d = 11; d >= 8; d--) {
        int s = (1 << d) - 1, M = 1 << d;
        dim3 grid(M / 64, 10);
        mma_level<5, 1><<<grid, 128>>>(s, M, nullptr, nullptr);
    }

    // d=7,6: scalar fused, BM=16, ROWS=2 (128 thr)
    for (int d = 7; d >= 6; d--) {
        int s = (1 << d) - 1, M = 1 << d;
        dim3 grid(M / 16, (HIDDEN + 15) / 16);
        fused_level<5, 1, 16, 16, 2><<<grid, 128>>>(s, M, nullptr, nullptr);
    }

    // d=5..0: warp per (node, j)
    for (int d = 5; d >= 0; d--) {
        int s = (1 << d) - 1, M = 1 << d;
        int warps = M * HIDDEN;
        int blocks = (warps + 7) / 8;
        warp_level<<<blocks, 256>>>(s, M);
    }

    // final loss over all 8191 nodes
    {
        int blocks = (NN + 7) / 8;
        loss_kernel<<<blocks, 256>>>(Why, by, scores, out);
    }
    (void)in_sizes; (void)n_in; (void)out_size;
}

// round 14
// speedup vs baseline: 1.7349x; 1.0775x over previous
#include <cuda_runtime.h>
#include <math.h>
#include <stdint.h>

#define HIDDEN 150
#define EMBED 300
#define OUTC 5
#define DEPTH 13
#define NN 8191          // 2^13 - 1
#define LL 4096          // leaves
#define LEAF_START 4095  // 2^12 - 1
#define KPAD 312         // K padded to 13 * 24
#define NPAD_L 480       // padded leaf columns (>= 152*3)
#define NPAD_U 800       // padded inner columns (>= 152*5)

// ---------------- device scratch (no allocs allowed) ----------------
__device__ float g_H[NN * HIDDEN + 64];   // small pad for safety
__device__ float g_C[NN * HIDDEN];
// transposed, gate-interleaved, K- and N-padded TF32 weights: WT[k][n], n = j*GATES + g
__device__ float g_WLt[KPAD * NPAD_L];
__device__ float g_WUt[KPAD * NPAD_U];
// row-major fp32 copy for warp_level tail
__device__ float g_WUi[750 * EMBED];
__device__ float g_bLi[480];
__device__ float g_bUi[800];

__device__ __forceinline__ float sigmoidf(float x) {
    return 1.0f / (1.0f + expf(-x));
}
__device__ __forceinline__ float to_tf32(float v) {
    float r;
    asm("cvt.rna.tf32.f32 %0, %1;" : "=f"(r) : "f"(v));
    return r;
}
__device__ __forceinline__ unsigned smem_u32(const void* p) {
    return (unsigned)__cvta_generic_to_shared(p);
}
__device__ __forceinline__ void cp_async16(unsigned dst, const void* src) {
    asm volatile("cp.async.ca.shared.global [%0], [%1], 16;" :: "r"(dst), "l"(src));
}
__device__ __forceinline__ void cp_async8(unsigned dst, const void* src) {
    asm volatile("cp.async.ca.shared.global [%0], [%1], 8;" :: "r"(dst), "l"(src));
}
__device__ __forceinline__ void cp_async8_sz(unsigned dst, const void* src, int sz) {
    asm volatile("cp.async.ca.shared.global [%0], [%1], 8, %2;" :: "r"(dst), "l"(src), "r"(sz));
}
__device__ __forceinline__ void cp_async_commit() {
    asm volatile("cp.async.commit_group;" ::: "memory");
}
__device__ __forceinline__ void cp_async_wait0() {
    asm volatile("cp.async.wait_group 0;" ::: "memory");
}
__device__ __forceinline__ void mma_tf32(float& c0, float& c1, float& c2, float& c3,
                                         unsigned a0, unsigned a1, unsigned a2, unsigned a3,
                                         unsigned b0, unsigned b1) {
    asm volatile(
        "mma.sync.aligned.m16n8k8.row.col.f32.tf32.tf32.f32 "
        "{%0,%1,%2,%3}, {%4,%5,%6,%7}, {%8,%9}, {%0,%1,%2,%3};"
        : "+f"(c0), "+f"(c1), "+f"(c2), "+f"(c3)
        : "r"(a0), "r"(a1), "r"(a2), "r"(a3), "r"(b0), "r"(b1));
}

// ---------------- weight stacking (tf32, K- and N-padded) ----------------
__global__ void prep_kernel(
    const float* __restrict__ Wi, const float* __restrict__ bi,
    const float* __restrict__ Wo, const float* __restrict__ bo,
    const float* __restrict__ Wu, const float* __restrict__ bu,
    const float* __restrict__ U0i, const float* __restrict__ U1i, const float* __restrict__ bbi,
    const float* __restrict__ U00f, const float* __restrict__ U01f,
    const float* __restrict__ U10f, const float* __restrict__ U11f, const float* __restrict__ bbf,
    const float* __restrict__ U0o, const float* __restrict__ U1o, const float* __restrict__ bbo,
    const float* __restrict__ U0u, const float* __restrict__ U1u, const float* __restrict__ bbu)
{
    int t = blockIdx.x * blockDim.x + threadIdx.x;
    int stride = gridDim.x * blockDim.x;

    for (int idx = t; idx < KPAD * NPAD_L; idx += stride) {
        int k = idx / NPAD_L, n = idx % NPAD_L;
        float v = 0.0f;
        if (n < 450 && k < EMBED) {
            int j = n / 3, g = n % 3;
            const float* W = (g == 0) ? Wi : (g == 1) ? Wo : Wu;
            v = to_tf32(W[j * EMBED + k]);
        }
        g_WLt[idx] = v;
    }
    for (int idx = t; idx < KPAD * NPAD_U; idx += stride) {
        int k = idx / NPAD_U, n = idx % NPAD_U;
        float v = 0.0f;
        if (n < 750 && k < EMBED) {
            int j = n / 5, g = n % 5;
            const float* U0; const float* U1;
            switch (g) {
                case 0:  U0 = U0i;  U1 = U1i;  break;
                case 1:  U0 = U00f; U1 = U01f; break;
                case 2:  U0 = U10f; U1 = U11f; break;
                case 3:  U0 = U0o;  U1 = U1o;  break;
                default: U0 = U0u;  U1 = U1u;  break;
            }
            float raw = (k < HIDDEN) ? U0[j * HIDDEN + k] : U1[j * HIDDEN + (k - HIDDEN)];
            g_WUi[n * EMBED + k] = raw;   // full-precision copy for warp_level
            v = to_tf32(raw);
        }
        g_WUt[idx] = v;
    }
    if (t < 480) {
        float v = 0.0f;
        if (t < 450) {
            int j = t / 3, g = t % 3;
            v = (g == 0) ? bi[j] : (g == 1) ? bo[j] : bu[j];
        }
        g_bLi[t] = v;
    }
    if (t < 800) {
        float v = 0.0f;
        if (t < 750) {
            int j = t / 5, g = t % 5;
            v = (g == 0) ? bbi[j] : (g <= 2) ? bbf[j] : (g == 3) ? bbo[j] : bbu[j];
        }
        g_bUi[t] = v;
    }
}

// ---------------- tensor-core fused level (tf32 mma.sync) ----------------
// Block: 128 threads = 4 warps, each warp owns a 16-row slice of BM=64.
// Tile: BM=64 x BN=(8 j's * GATES); K tiles of 24 (3 k8 steps), double-buffered.
template<int GATES, int MODE>
__global__ __launch_bounds__(128)
void mma_level(int s, int M,
               const float* __restrict__ emb,
               const int* __restrict__ words)
{
    constexpr int BM = 64, BJ = 8;
    constexpr int BN = BJ * GATES;          // 24 leaf / 40 inner
    constexpr int NT8 = BN / 8;             // 3 / 5
    constexpr int BK = 24;
    constexpr int NT = KPAD / BK;           // 13
    constexpr int AP = 28;                  // A smem row stride (conflict-free, 16B-aligned)
    constexpr int WP = 44;                  // W smem row stride (conflict-free, 16B-aligned)
    constexpr int NPAD = (MODE == 0) ? NPAD_L : NPAD_U;

    constexpr int ACH = BM * (BK / 2);      // 8B chunks for A: 768
    constexpr int LAC = ACH / 128;          // 6
    constexpr int WCH = BK * (BN / 4);      // 16B chunks for W: 144 / 240
    constexpr int LWC = (WCH + 127) / 128;  // 2 (wrap-safe: 256 < 2*WCH)

    constexpr int ABUF = BM * AP;           // floats per A buffer
    constexpr int WBUF = BK * WP;
    constexpr int SMEMFL = 2 * ABUF + 2 * WBUF;

    __shared__ __align__(16) float SB[SMEMFL];
    __shared__ int rowOff[BM];

    float* AsF = SB;
    float* WsF = SB + 2 * ABUF;
    float* Cs  = SB;                        // overlay, used after the K loop

    const float* __restrict__ WT    = (MODE == 0) ? g_WLt : g_WUt;
    const float* __restrict__ Abase = (MODE == 0) ? emb : g_H;
    const float* __restrict__ bias  = (MODE == 0) ? g_bLi : g_bUi;

    int tid = threadIdx.x;
    int warp = tid >> 5, lane = tid & 31;
    int gid = lane >> 2, tig = lane & 3;
    int m0 = warp * 16;
    int bm = blockIdx.x * BM;
    int j0 = blockIdx.y * BJ;
    int n0 = j0 * GATES;

    for (int e = tid; e < BM; e += 128) {
        int m = bm + e;
        rowOff[e] = (MODE == 0) ? words[LEAF_START + m] * EMBED
                                : (2 * s + 1) * HIDDEN + m * EMBED;
    }
    __syncthreads();

    // ---- A chunk tables: 8B chunks, 12 per row ----
    int aSrc[LAC]; unsigned aDst[LAC]; int aLastB[LAC];
    #pragma unroll
    for (int l = 0; l < LAC; l++) {
        int idx = tid + l * 128;
        int m = idx / 12, c = idx % 12;
        aSrc[l] = rowOff[m] + 2 * c;
        aDst[l] = smem_u32(AsF) + (unsigned)((m * AP + 2 * c) * 4);
        int rem = (12 - 2 * c) * 4;        // valid bytes in last tile (k0=288, 12 valid floats)
        aLastB[l] = rem < 0 ? 0 : (rem > 8 ? 8 : rem);
    }
    // ---- W chunk tables: 16B chunks ----
    int wSrc[LWC]; unsigned wDst[LWC];
    #pragma unroll
    for (int l = 0; l < LWC; l++) {
        int idx = tid + l * 128;
        if (idx >= WCH) idx -= WCH;        // wrap: benign duplicate copy
        int kk = idx / (BN / 4), n4 = idx % (BN / 4);
        wSrc[l] = kk * NPAD + n0 + n4 * 4;
        wDst[l] = smem_u32(WsF) + (unsigned)((kk * WP + n4 * 4) * 4);
    }

    auto fetch = [&](int t, int b) {
        int k0 = t * BK;
        unsigned aoff = (unsigned)(b * ABUF * 4);
        if (t == NT - 1) {
            #pragma unroll
            for (int l = 0; l < LAC; l++) {
                const float* src = Abase + (aLastB[l] > 0 ? aSrc[l] + k0 : aSrc[l]);
                cp_async8_sz(aDst[l] + aoff, src, aLastB[l]);
            }
        } else {
            #pragma unroll
            for (int l = 0; l < LAC; l++)
                cp_async8(aDst[l] + aoff, Abase + aSrc[l] + k0);
        }
        unsigned woff = (unsigned)(b * WBUF * 4);
        int wk = k0 * NPAD;
        #pragma unroll
        for (int l = 0; l < LWC; l++)
            cp_async16(wDst[l] + woff, WT + wSrc[l] + wk);
        cp_async_commit();
    };

    float c[NT8][4];
    #pragma unroll
    for (int nt = 0; nt < NT8; nt++)
        #pragma unroll
        for (int q = 0; q < 4; q++)
            c[nt][q] = 0.0f;

    fetch(0, 0);
    cp_async_wait0();
    __syncthreads();

    #pragma unroll 1
    for (int t = 0; t < NT; t++) {
        int b = t & 1;
        if (t + 1 < NT) fetch(t + 1, b ^ 1);

        const float* Ab = AsF + b * ABUF;
        const float* Wb = WsF + b * WBUF;
        #pragma unroll
        for (int ks = 0; ks < 3; ks++) {
            int kb = ks * 8;
            unsigned a0 = __float_as_uint(to_tf32(Ab[(m0 + gid) * AP + kb + tig]));
            unsigned a1 = __float_as_uint(to_tf32(Ab[(m0 + gid + 8) * AP + kb + tig]));
            unsigned a2 = __float_as_uint(to_tf32(Ab[(m0 + gid) * AP + kb + tig + 4]));
            unsigned a3 = __float_as_uint(to_tf32(Ab[(m0 + gid + 8) * AP + kb + tig + 4]));
            #pragma unroll
            for (int nt = 0; nt < NT8; nt++) {
                unsigned b0 = __float_as_uint(Wb[(kb + tig) * WP + nt * 8 + gid]);
                unsigned b1 = __float_as_uint(Wb[(kb + tig + 4) * WP + nt * 8 + gid]);
                mma_tf32(c[nt][0], c[nt][1], c[nt][2], c[nt][3], a0, a1, a2, a3, b0, b1);
            }
        }
        if (t + 1 < NT) cp_async_wait0();
        __syncthreads();
    }

    // ---- C fragments -> smem (overlay) ----
    #pragma unroll
    for (int nt = 0; nt < NT8; nt++) {
        Cs[(m0 + gid) * WP + nt * 8 + tig * 2]         = c[nt][0];
        Cs[(m0 + gid) * WP + nt * 8 + tig * 2 + 1]     = c[nt][1];
        Cs[(m0 + gid + 8) * WP + nt * 8 + tig * 2]     = c[nt][2];
        Cs[(m0 + gid + 8) * WP + nt * 8 + tig * 2 + 1] = c[nt][3];
    }
    __syncthreads();

    // ---- fused activation epilogue ----
    #pragma unroll
    for (int it = 0; it < (BM * BJ) / 128; it++) {
        int idx = tid + it * 128;
        int jl = idx >> 6;          // 0..7
        int m = idx & 63;
        int j = j0 + jl;
        if (j >= HIDDEN) continue;
        int nb = j * GATES;
        const float* cv = Cs + m * WP + jl * GATES;
        if (MODE == 0) {
            float ig = sigmoidf(cv[0] + bias[nb + 0]);
            float og = sigmoidf(cv[1] + bias[nb + 1]);
            float uv = tanhf   (cv[2] + bias[nb + 2]);
            float cc = ig * uv;
            float h = og * tanhf(cc);
            int node = LEAF_START + bm + m;
            g_H[node * HIDDEN + j] = h;
            g_C[node * HIDDEN + j] = cc;
        } else {
            float ig = sigmoidf(cv[0] + bias[nb + 0]);
            float fl = sigmoidf(cv[1] + bias[nb + 1]);
            float fr = sigmoidf(cv[2] + bias[nb + 2]);
            float og = sigmoidf(cv[3] + bias[nb + 3]);
            float uv = tanhf   (cv[4] + bias[nb + 4]);
            int node = s + bm + m;
            float lc = g_C[(2 * node + 1) * HIDDEN + j];
            float rc = g_C[(2 * node + 2) * HIDDEN + j];
            float cc = ig * uv + fl * lc + fr * rc;
            float h = og * tanhf(cc);
            g_H[node * HIDDEN + j] = h;
            g_C[node * HIDDEN + j] = cc;
        }
    }
}

// ---------------- scalar fused level (for small levels d7,d6) ----------------
template<int GATES, int MODE, int BM, int BJ, int ROWS>
__global__ __launch_bounds__((BM / ROWS) * BJ)
void fused_level(int s, int M,
                 const float* __restrict__ emb,
                 const int* __restrict__ words)
{
    constexpr int THREADS = (BM / ROWS) * BJ;
    constexpr int WCOLS = BJ * GATES;
    constexpr int NTOTP = (MODE == 0) ? NPAD_L : NPAD_U;
    constexpr int BKS = 20;
    constexpr int AELEMS = BM * BKS;
    constexpr int WELEMS = WCOLS * BKS;
    constexpr int LA = (AELEMS + THREADS - 1) / THREADS;
    constexpr int LW = (WELEMS + THREADS - 1) / THREADS;
    constexpr int NTS = EMBED / BKS;   // 15

    __shared__ float As[2][BKS][BM];
    __shared__ float Ws[2][BKS][WCOLS];
    __shared__ int rowOff[BM];

    const float* __restrict__ WT    = (MODE == 0) ? g_WLt : g_WUt;
    const float* __restrict__ Abase = (MODE == 0) ? emb : (g_H + (2 * s + 1) * HIDDEN);
    const float* __restrict__ bias  = (MODE == 0) ? g_bLi : g_bUi;

    int bm = blockIdx.x * BM;
    int j0 = blockIdx.y * BJ;
    int n0 = j0 * GATES;
    int tid = threadIdx.x;
    int tx = tid % BJ, ty = tid / BJ;

    for (int e = tid; e < BM; e += THREADS) {
        int m = bm + e;
        rowOff[e] = (MODE == 0) ? words[LEAF_START + m] * EMBED : m * EMBED;
    }
    __syncthreads();

    int aGOff[LA], aSOff[LA];
    #pragma unroll
    for (int l = 0; l < LA; l++) {
        int e = tid + l * THREADS;
        if (e >= AELEMS) e -= AELEMS;
        int ml = e / BKS, kk = e % BKS;
        aGOff[l] = rowOff[ml] + kk;
        aSOff[l] = kk * BM + ml;
    }
    int wGOff[LW], wSOff[LW];
    #pragma unroll
    for (int l = 0; l < LW; l++) {
        int e = tid + l * THREADS;
        if (e >= WELEMS) e -= WELEMS;
        int kk = e / WCOLS, nl = e % WCOLS;
        // NOTE: weights are in KPAD-row layout; row stride NTOTP unchanged
        wGOff[l] = kk * NTOTP + n0 + nl;
        wSOff[l] = kk * WCOLS + nl;
    }

    float* AsF = &As[0][0][0];
    float* WsF = &Ws[0][0][0];
    constexpr int ABUF = BKS * BM;
    constexpr int WBUF = BKS * WCOLS;

    float ra[LA], rw[LW];
    auto fetch = [&](int k0) {
        #pragma unroll
        for (int l = 0; l < LA; l++) ra[l] = Abase[aGOff[l] + k0];
        int wk = k0 * NTOTP;
        #pragma unroll
        for (int l = 0; l < LW; l++) rw[l] = WT[wGOff[l] + wk];
    };
    auto stage = [&](int boff_a, int boff_w) {
        #pragma unroll
        for (int l = 0; l < LA; l++) AsF[boff_a + aSOff[l]] = ra[l];
        #pragma unroll
        for (int l = 0; l < LW; l++) WsF[boff_w + wSOff[l]] = rw[l];
    };

    float acc[ROWS][GATES];
    #pragma unroll
    for (int i = 0; i < ROWS; i++)
        #pragma unroll
        for (int g = 0; g < GATES; g++)
            acc[i][g] = 0.0f;

    fetch(0);
    stage(0, 0);
    __syncthreads();

    #pragma unroll 1
    for (int t = 0; t < NTS; t++) {
        int b = t & 1;
        if (t + 1 < NTS) fetch((t + 1) * BKS);
        const float* Ab = AsF + b * ABUF;
        const float* Wb = WsF + b * WBUF;
        #pragma unroll
        for (int kk = 0; kk < BKS; kk++) {
            float a[ROWS], w[GATES];
            #pragma unroll
            for (int i = 0; i < ROWS; i++) a[i] = Ab[kk * BM + ty * ROWS + i];
            #pragma unroll
            for (int g = 0; g < GATES; g++) w[g] = Wb[kk * WCOLS + tx * GATES + g];
            #pragma unroll
            for (int i = 0; i < ROWS; i++)
                #pragma unroll
                for (int g = 0; g < GATES; g++)
                    acc[i][g] += a[i] * w[g];
        }
        if (t + 1 < NTS) stage((b ^ 1) * ABUF, (b ^ 1) * WBUF);
        __syncthreads();
    }

    int j = j0 + tx;
    if (j >= HIDDEN) return;
    int nb = j * GATES;
    #pragma unroll
    for (int i = 0; i < ROWS; i++) {
        int m = bm + ty * ROWS + i;
        float ig = sigmoidf(acc[i][0] + bias[nb + 0]);
        float fl = sigmoidf(acc[i][1] + bias[nb + 1]);
        float fr = sigmoidf(acc[i][2] + bias[nb + 2]);
        float og = sigmoidf(acc[i][3] + bias[nb + 3]);
        float uv = tanhf   (acc[i][4] + bias[nb + 4]);
        int node = s + m;
        float lc = g_C[(2 * node + 1) * HIDDEN + j];
        float rc = g_C[(2 * node + 2) * HIDDEN + j];
        float cc = ig * uv + fl * lc + fr * rc;
        float h = og * tanhf(cc);
        g_H[node * HIDDEN + j] = h;
        g_C[node * HIDDEN + j] = cc;
    }
}

// ---------------- warp-per-(node, j) kernel for tiny levels ----------------
__global__ void warp_level(int s, int M)
{
    int wid  = (blockIdx.x * blockDim.x + threadIdx.x) >> 5;
    int lane = threadIdx.x & 31;
    int m = wid / HIDDEN;
    int j = wid % HIDDEN;
    if (m >= M) return;

    const float* __restrict__ A  = g_H + (2 * s + 1 + 2 * m) * HIDDEN;
    const float* __restrict__ Wr = g_WUi + (j * 5) * EMBED;

    float a0 = 0.f, a1 = 0.f, a2 = 0.f, a3 = 0.f, a4 = 0.f;
    #pragma unroll
    for (int kb = 0; kb < EMBED; kb += 32) {
        int k = kb + lane;
        float a = A[k];
        a0 += a * Wr[k];
        a1 += a * Wr[EMBED + k];
        a2 += a * Wr[2 * EMBED + k];
        a3 += a * Wr[3 * EMBED + k];
        a4 += a * Wr[4 * EMBED + k];
    }
    #pragma unroll
    for (int d = 16; d > 0; d >>= 1) {
        a0 += __shfl_xor_sync(0xffffffff, a0, d);
        a1 += __shfl_xor_sync(0xffffffff, a1, d);
        a2 += __shfl_xor_sync(0xffffffff, a2, d);
        a3 += __shfl_xor_sync(0xffffffff, a3, d);
        a4 += __shfl_xor_sync(0xffffffff, a4, d);
    }
    if (lane == 0) {
        int nb = j * 5;
        float ig = sigmoidf(a0 + g_bUi[nb + 0]);
        float fl = sigmoidf(a1 + g_bUi[nb + 1]);
        float fr = sigmoidf(a2 + g_bUi[nb + 2]);
        float og = sigmoidf(a3 + g_bUi[nb + 3]);
        float uv = tanhf   (a4 + g_bUi[nb + 4]);
        int node = s + m;
        float lc = g_C[(2 * node + 1) * HIDDEN + j];
        float rc = g_C[(2 * node + 2) * HIDDEN + j];
        float c = ig * uv + fl * lc + fr * rc;
        float h = og * tanhf(c);
        g_H[node * HIDDEN + j] = h;
        g_C[node * HIDDEN + j] = c;
    }
}

// ---------------- loss ----------------
__global__ void zero_out(float* out)
{
    if (threadIdx.x == 0 && blockIdx.x == 0) out[0] = 0.0f;
}

__global__ void loss_kernel(const float* __restrict__ Why,
                            const float* __restrict__ by,
                            const int*   __restrict__ scores,
                            float* __restrict__ out)
{
    int gw   = (blockIdx.x * blockDim.x + threadIdx.x) >> 5;
    int lane = threadIdx.x & 31;
    if (gw >= NN) return;

    const float* h = g_H + gw * HIDDEN;
    float logits[OUTC];
    #pragma unroll
    for (int o = 0; o < OUTC; o++) {
        float sacc = 0.0f;
        for (int k = lane; k < HIDDEN; k += 32)
            sacc += Why[o * HIDDEN + k] * h[k];
        #pragma unroll
        for (int d = 16; d > 0; d >>= 1)
            sacc += __shfl_xor_sync(0xffffffff, sacc, d);
        logits[o] = sacc + by[o];
    }
    if (lane == 0) {
        float mx = logits[0];
        #pragma unroll
        for (int o = 1; o < OUTC; o++) mx = fmaxf(mx, logits[o]);
        float se = 0.0f;
        #pragma unroll
        for (int o = 0; o < OUTC; o++) se += expf(logits[o] - mx);
        float lse = mx + logf(se);
        int sc = scores[gw];
        atomicAdd(out, lse - logits[sc]);
    }
}

// ---------------- launch ----------------
extern "C" void kernel_launch(void* const* d_in, const int* in_sizes, int n_in,
                              void* d_out, int out_size)
{
    const float* Wi   = (const float*)d_in[0];
    const float* bi   = (const float*)d_in[1];
    const float* Wo   = (const float*)d_in[2];
    const float* bo   = (const float*)d_in[3];
    const float* Wu   = (const float*)d_in[4];
    const float* bu   = (const float*)d_in[5];
    const float* U0i  = (const float*)d_in[6];
    const float* U1i  = (const float*)d_in[7];
    const float* bbi  = (const float*)d_in[8];
    const float* U00f = (const float*)d_in[9];
    const float* U01f = (const float*)d_in[10];
    const float* U10f = (const float*)d_in[11];
    const float* U11f = (const float*)d_in[12];
    const float* bbf  = (const float*)d_in[13];
    const float* U0o  = (const float*)d_in[14];
    const float* U1o  = (const float*)d_in[15];
    const float* bbo  = (const float*)d_in[16];
    const float* U0u  = (const float*)d_in[17];
    const float* U1u  = (const float*)d_in[18];
    const float* bbu  = (const float*)d_in[19];
    const float* Why  = (const float*)d_in[20];
    const float* by   = (const float*)d_in[21];
    const float* emb  = (const float*)d_in[22];
    const int*   scores = (const int*)d_in[23];
    const int*   words  = (const int*)d_in[24];

    float* out = (float*)d_out;

    zero_out<<<1, 32>>>(out);
    prep_kernel<<<240, 256>>>(Wi, bi, Wo, bo, Wu, bu,
                              U0i, U1i, bbi,
                              U00f, U01f, U10f, U11f, bbf,
                              U0o, U1o, bbo,
                              U0u, U1u, bbu);

    const int GY = (HIDDEN + 7) / 8;   // 19

    // leaf: M=4096 — tensor cores, grid (64, 19)
    {
        dim3 grid(LL / 64, GY);
        mma_level<3, 0><<<grid, 128>>>(0, LL, emb, words);
    }

    // d=11..8: tensor cores — grids (32..4, 19)
    for (int d = 11; d >= 8; d--) {
        int s = (1 << d) - 1, M = 1 << d;
        dim3 grid(M / 64, GY);
        mma_level<5, 1><<<grid, 128>>>(s, M, nullptr, nullptr);
    }

    // d=7,6: scalar fused, BM=16, ROWS=2 (128 thr)
    for (int d = 7; d >= 6; d--) {
        int s = (1 << d) - 1, M = 1 << d;
        dim3 grid(M / 16, (HIDDEN + 15) / 16);
        fused_level<5, 1, 16, 16, 2><<<grid, 128>>>(s, M, nullptr, nullptr);
    }

    // d=5..0: warp per (node, j)
    for (int d = 5; d >= 0; d--) {
        int s = (1 << d) - 1, M = 1 << d;
        int warps = M * HIDDEN;
        int blocks = (warps + 7) / 8;
        warp_level<<<blocks, 256>>>(s, M);
    }

    // final loss over all 8191 nodes
    {
        int blocks = (NN + 7) / 8;
        loss_kernel<<<blocks, 256>>>(Why, by, scores, out);
    }
    (void)in_sizes; (void)n_in; (void)out_size;
}